// round 1
// baseline (speedup 1.0000x reference)
#include <cuda_runtime.h>

#define NN 100000
#define NE 3200000
#define HID 16

// ---------------- scratch (allowed: __device__ globals) ----------------
__device__ float g_e[NE][HID];        // 204.8 MB edge features
__device__ float g_agg_s[NN][HID];    // 6.4 MB
__device__ float g_agg_r[NN][HID];    // 6.4 MB
__device__ float g_nodes[NN];
__device__ unsigned int g_norm_bits;

__device__ __forceinline__ void red_add_v4(float* p, float a, float b, float c, float d) {
    asm volatile("red.global.add.v4.f32 [%0], {%1, %2, %3, %4};"
                 :: "l"(p), "f"(a), "f"(b), "f"(c), "f"(d) : "memory");
}

// ---------------- init: zero agg buffers + norm accumulator ----------------
__global__ void k_zero() {
    int i = blockIdx.x * blockDim.x + threadIdx.x;
    if (i == 0) g_norm_bits = 0u;
    const int nf4 = NN * HID / 4;
    float4 z = make_float4(0.f, 0.f, 0.f, 0.f);
    if (i < nf4) {
        ((float4*)g_agg_s)[i] = z;
        ((float4*)g_agg_r)[i] = z;
    }
}

// ---------------- norm = max |edges_init| (exact: max is order-independent) ----------------
__global__ void k_norm(const float* __restrict__ x) {
    float m = 0.f;
    for (int i = blockIdx.x * blockDim.x + threadIdx.x; i < NE; i += gridDim.x * blockDim.x)
        m = fmaxf(m, fabsf(x[i]));
#pragma unroll
    for (int o = 16; o; o >>= 1) m = fmaxf(m, __shfl_xor_sync(0xffffffffu, m, o));
    if ((threadIdx.x & 31) == 0) atomicMax(&g_norm_bits, __float_as_uint(m));
}

// ---------------- encoder: e = MLP(x/norm), store e, scatter to aggs ----------------
__global__ __launch_bounds__(256) void k_enc(
    const float* __restrict__ edges_init,
    const int* __restrict__ senders, const int* __restrict__ receivers,
    const float* __restrict__ w1g, const float* __restrict__ b1g,
    const float* __restrict__ w2g, const float* __restrict__ b2g)
{
    __shared__ float w1[HID], b1[HID], w2[HID * HID], b2[HID];
    int t = threadIdx.x;
    if (t < HID) { w1[t] = w1g[t]; b1[t] = b1g[t]; b2[t] = b2g[t]; }
    for (int i = t; i < HID * HID; i += blockDim.x) w2[i] = w2g[i];
    __syncthreads();

    int i = blockIdx.x * blockDim.x + t;
    if (i >= NE) return;

    float x = edges_init[i] / __uint_as_float(g_norm_bits);
    float h[HID];
#pragma unroll
    for (int j = 0; j < HID; j++) h[j] = fmaxf(fmaf(w1[j], x, b1[j]), 0.f);
    float e[HID];
#pragma unroll
    for (int j = 0; j < HID; j++) {
        float a = b2[j];
#pragma unroll
        for (int k = 0; k < HID; k++) a = fmaf(w2[j * HID + k], h[k], a);
        e[j] = a;
    }

    float4* ep = (float4*)g_e[i];
#pragma unroll
    for (int q = 0; q < 4; q++)
        ep[q] = make_float4(e[4 * q], e[4 * q + 1], e[4 * q + 2], e[4 * q + 3]);

    int s = senders[i], r = receivers[i];
    float* ps = g_agg_s[s];
    float* pr = g_agg_r[r];
#pragma unroll
    for (int q = 0; q < 4; q++) {
        red_add_v4(ps + 4 * q, e[4 * q], e[4 * q + 1], e[4 * q + 2], e[4 * q + 3]);
        red_add_v4(pr + 4 * q, e[4 * q], e[4 * q + 1], e[4 * q + 2], e[4 * q + 3]);
    }
}

// ---------------- node update: read aggs (and re-zero them), MLP 33->16->1 ----------------
template <bool FIRST>
__global__ __launch_bounds__(256) void k_node(
    const float* __restrict__ in_nodes,
    const float* __restrict__ w1g, const float* __restrict__ b1g,
    const float* __restrict__ w2g, const float* __restrict__ b2g)
{
    __shared__ float w1[HID * 33], b1[HID], w2[HID], b2s;
    int t = threadIdx.x;
    for (int i = t; i < HID * 33; i += blockDim.x) w1[i] = w1g[i];
    if (t < HID) { b1[t] = b1g[t]; w2[t] = w2g[t]; }
    if (t == 0) b2s = b2g[0];
    __syncthreads();

    int n = blockIdx.x * blockDim.x + t;
    if (n >= NN) return;

    float xin[33];
    xin[0] = FIRST ? in_nodes[n] : g_nodes[n];
    float4* as4 = (float4*)g_agg_s[n];
    float4* ar4 = (float4*)g_agg_r[n];
#pragma unroll
    for (int q = 0; q < 4; q++) {
        float4 v = as4[q];
        xin[1 + 4 * q] = v.x; xin[2 + 4 * q] = v.y;
        xin[3 + 4 * q] = v.z; xin[4 + 4 * q] = v.w;
        float4 w = ar4[q];
        xin[17 + 4 * q] = w.x; xin[18 + 4 * q] = w.y;
        xin[19 + 4 * q] = w.z; xin[20 + 4 * q] = w.w;
    }
    // re-zero aggs for the next scatter round (next scatter launches after us)
    float4 z = make_float4(0.f, 0.f, 0.f, 0.f);
#pragma unroll
    for (int q = 0; q < 4; q++) { as4[q] = z; ar4[q] = z; }

    float out = b2s;
#pragma unroll
    for (int j = 0; j < HID; j++) {
        float hj = b1[j];
#pragma unroll
        for (int c = 0; c < 33; c++) hj = fmaf(w1[j * 33 + c], xin[c], hj);
        out = fmaf(w2[j], fmaxf(hj, 0.f), out);
    }
    g_nodes[n] = out;
}

// ---------------- edge update (+scatter, or fused decoder+residual on last round) ----------------
template <bool LAST>
__global__ __launch_bounds__(256) void k_edge(
    const int* __restrict__ senders, const int* __restrict__ receivers,
    const float* __restrict__ ew1g, const float* __restrict__ eb1g,
    const float* __restrict__ ew2g, const float* __restrict__ eb2g,
    const float* __restrict__ dw1g, const float* __restrict__ db1g,
    const float* __restrict__ dw2g, const float* __restrict__ db2g,
    const float* __restrict__ edges_init, const float* __restrict__ alpha_p,
    float* __restrict__ out)
{
    __shared__ float ew1[HID * 18], eb1[HID], ew2[HID * HID], eb2[HID];
    __shared__ float dw1[HID * HID], db1[HID], dw2[HID], db2s, alphas;
    int t = threadIdx.x;
    for (int i = t; i < HID * 18; i += blockDim.x) ew1[i] = ew1g[i];
    for (int i = t; i < HID * HID; i += blockDim.x) ew2[i] = ew2g[i];
    if (t < HID) { eb1[t] = eb1g[t]; eb2[t] = eb2g[t]; }
    if (LAST) {
        for (int i = t; i < HID * HID; i += blockDim.x) dw1[i] = dw1g[i];
        if (t < HID) { db1[t] = db1g[t]; dw2[t] = dw2g[t]; }
        if (t == 0) { db2s = db2g[0]; alphas = alpha_p[0]; }
    }
    __syncthreads();

    int i = blockIdx.x * blockDim.x + t;
    if (i >= NE) return;

    float e[HID];
    float4* ep = (float4*)g_e[i];
#pragma unroll
    for (int q = 0; q < 4; q++) {
        float4 v = ep[q];
        e[4 * q] = v.x; e[4 * q + 1] = v.y; e[4 * q + 2] = v.z; e[4 * q + 3] = v.w;
    }
    int s = senders[i], r = receivers[i];
    float ns = g_nodes[s], nr = g_nodes[r];

    float h[HID];
#pragma unroll
    for (int j = 0; j < HID; j++) {
        float a = eb1[j];
#pragma unroll
        for (int k = 0; k < HID; k++) a = fmaf(ew1[j * 18 + k], e[k], a);
        a = fmaf(ew1[j * 18 + 16], ns, a);
        a = fmaf(ew1[j * 18 + 17], nr, a);
        h[j] = fmaxf(a, 0.f);
    }
    float e2[HID];
#pragma unroll
    for (int j = 0; j < HID; j++) {
        float a = eb2[j];
#pragma unroll
        for (int k = 0; k < HID; k++) a = fmaf(ew2[j * HID + k], h[k], a);
        e2[j] = a;
    }

    if (!LAST) {
#pragma unroll
        for (int q = 0; q < 4; q++)
            ep[q] = make_float4(e2[4 * q], e2[4 * q + 1], e2[4 * q + 2], e2[4 * q + 3]);
        float* ps = g_agg_s[s];
        float* pr = g_agg_r[r];
#pragma unroll
        for (int q = 0; q < 4; q++) {
            red_add_v4(ps + 4 * q, e2[4 * q], e2[4 * q + 1], e2[4 * q + 2], e2[4 * q + 3]);
            red_add_v4(pr + 4 * q, e2[4 * q], e2[4 * q + 1], e2[4 * q + 2], e2[4 * q + 3]);
        }
    } else {
        float h2[HID];
#pragma unroll
        for (int j = 0; j < HID; j++) {
            float a = db1[j];
#pragma unroll
            for (int k = 0; k < HID; k++) a = fmaf(dw1[j * HID + k], e2[k], a);
            h2[j] = fmaxf(a, 0.f);
        }
        float sdec = db2s;
#pragma unroll
        for (int k = 0; k < HID; k++) sdec = fmaf(dw2[k], h2[k], sdec);
        float nrm = __uint_as_float(g_norm_bits);
        out[i] = fmaf(alphas * nrm, sdec, edges_init[i]);
    }
}

// ---------------- launch ----------------
extern "C" void kernel_launch(void* const* d_in, const int* in_sizes, int n_in,
                              void* d_out, int out_size)
{
    const float* nodes      = (const float*)d_in[0];
    const float* edges_init = (const float*)d_in[1];
    const int*   senders    = (const int*)d_in[2];
    const int*   receivers  = (const int*)d_in[3];
    const float* enc_w1 = (const float*)d_in[4];
    const float* enc_b1 = (const float*)d_in[5];
    const float* enc_w2 = (const float*)d_in[6];
    const float* enc_b2 = (const float*)d_in[7];
    const float* node_w1 = (const float*)d_in[8];
    const float* node_b1 = (const float*)d_in[9];
    const float* node_w2 = (const float*)d_in[10];
    const float* node_b2 = (const float*)d_in[11];
    const float* edge_w1 = (const float*)d_in[12];
    const float* edge_b1 = (const float*)d_in[13];
    const float* edge_w2 = (const float*)d_in[14];
    const float* edge_b2 = (const float*)d_in[15];
    const float* dec_w1 = (const float*)d_in[16];
    const float* dec_b1 = (const float*)d_in[17];
    const float* dec_w2 = (const float*)d_in[18];
    const float* dec_b2 = (const float*)d_in[19];
    const float* alpha  = (const float*)d_in[20];
    float* out = (float*)d_out;

    const int TB = 256;
    int zb = (NN * HID / 4 + TB - 1) / TB;
    k_zero<<<zb, TB>>>();
    k_norm<<<1024, TB>>>(edges_init);

    int eb = (NE + TB - 1) / TB;
    int nb = (NN + TB - 1) / TB;

    k_enc<<<eb, TB>>>(edges_init, senders, receivers, enc_w1, enc_b1, enc_w2, enc_b2);

    for (int r = 0; r < 3; r++) {
        if (r == 0)
            k_node<true><<<nb, TB>>>(nodes, node_w1, node_b1, node_w2, node_b2);
        else
            k_node<false><<<nb, TB>>>(nodes, node_w1, node_b1, node_w2, node_b2);

        if (r < 2)
            k_edge<false><<<eb, TB>>>(senders, receivers,
                                      edge_w1, edge_b1, edge_w2, edge_b2,
                                      dec_w1, dec_b1, dec_w2, dec_b2,
                                      edges_init, alpha, out);
        else
            k_edge<true><<<eb, TB>>>(senders, receivers,
                                     edge_w1, edge_b1, edge_w2, edge_b2,
                                     dec_w1, dec_b1, dec_w2, dec_b2,
                                     edges_init, alpha, out);
    }
}